// round 10
// baseline (speedup 1.0000x reference)
#include <cuda_runtime.h>
#include <cstdint>

#define T_SEQ 16384
#define HDIM  512
#define G4    2048
#define NC    16     // cluster size = whole grid (all-to-all via DSMEM)
#define TPB   512    // 16 warps per CTA
#define UPC   32     // units per CTA

// Precomputed input gates (allocation-guard-legal scratch)
__device__ float g_xgates[(size_t)T_SEQ * G4];

// ---------------------------------------------------------------------------
// GEMM: g_xgates[t][j] = dot(input[t,:], w_ih[j,:]) + b_ih[j]  (unchanged)
// ---------------------------------------------------------------------------
__global__ __launch_bounds__(256) void gemm_xgates_kernel(
    const float* __restrict__ A, const float* __restrict__ W,
    const float* __restrict__ bias)
{
    __shared__ float As[8][128];
    __shared__ float Ws[8][128];
    const int bm = blockIdx.y * 128;
    const int bn = blockIdx.x * 128;
    const int tid = threadIdx.x;
    const int lr = tid >> 1;
    const int lc = (tid & 1) << 2;
    const int tx = tid & 15;
    const int ty = tid >> 4;

    float acc[8][8];
#pragma unroll
    for (int i = 0; i < 8; i++)
#pragma unroll
        for (int j = 0; j < 8; j++) acc[i][j] = 0.0f;

    const float* Aptr = A + (size_t)(bm + lr) * HDIM + lc;
    const float* Wptr = W + (size_t)(bn + lr) * HDIM + lc;

    for (int k0 = 0; k0 < HDIM; k0 += 8) {
        float4 av = *(const float4*)(Aptr + k0);
        float4 wv = *(const float4*)(Wptr + k0);
        __syncthreads();
        As[lc + 0][lr] = av.x; As[lc + 1][lr] = av.y;
        As[lc + 2][lr] = av.z; As[lc + 3][lr] = av.w;
        Ws[lc + 0][lr] = wv.x; Ws[lc + 1][lr] = wv.y;
        Ws[lc + 2][lr] = wv.z; Ws[lc + 3][lr] = wv.w;
        __syncthreads();
#pragma unroll
        for (int k = 0; k < 8; k++) {
            float a[8], b[8];
            *(float4*)(a)     = *(const float4*)&As[k][ty * 8];
            *(float4*)(a + 4) = *(const float4*)&As[k][ty * 8 + 4];
            *(float4*)(b)     = *(const float4*)&Ws[k][tx * 8];
            *(float4*)(b + 4) = *(const float4*)&Ws[k][tx * 8 + 4];
#pragma unroll
            for (int i = 0; i < 8; i++)
#pragma unroll
                for (int j = 0; j < 8; j++)
                    acc[i][j] = fmaf(a[i], b[j], acc[i][j]);
        }
    }

    float bb[8];
    *(float4*)(bb)     = *(const float4*)&bias[bn + tx * 8];
    *(float4*)(bb + 4) = *(const float4*)&bias[bn + tx * 8 + 4];
#pragma unroll
    for (int i = 0; i < 8; i++) {
        float* cp = g_xgates + (size_t)(bm + ty * 8 + i) * G4 + bn + tx * 8;
        float4 v0 = make_float4(acc[i][0] + bb[0], acc[i][1] + bb[1],
                                acc[i][2] + bb[2], acc[i][3] + bb[3]);
        float4 v1 = make_float4(acc[i][4] + bb[4], acc[i][5] + bb[5],
                                acc[i][6] + bb[6], acc[i][7] + bb[7]);
        *(float4*)cp       = v0;
        *(float4*)(cp + 4) = v1;
    }
}

// ---------------------------------------------------------------------------
// Cluster recurrent kernel: 16 CTAs x 512 threads, all-to-all h exchange
// via DSMEM push with parity-LSB tags.  NO per-step barriers of any kind.
// A trailing cluster barrier (THE R9 crash fix) keeps every CTA resident
// until all in-flight peer pushes have landed.
//
// CTA r owns units 32r..32r+31.  Warp w owns units 32r+2w (+half).
// Half-warp: lanes 0-15 -> unit u0, lanes 16-31 -> u1; lane covers cols
// [32*hl, 32*hl+32).  Weights: gates 0,1 in regs (64), gates 2,3 in smem.
// Per step: poll OWN smem (LDS) for parity-tagged h_{t-1}, FMA directly
// from polled registers, butterfly in the half, MUFU activations, then the
// 16 lanes of each half push h (LSB=parity) to the 16 CTAs' smem rings.
// ---------------------------------------------------------------------------
#define HBUF_WORDS 576         // 512 + 4 pad words per 32 (LDS.128 phase-clean)
#define WSM_STRIDE 68          // 64 weights + 4 pad (16B-aligned, phase-clean)
#define SMEM_BYTES ((2 * HBUF_WORDS + TPB * WSM_STRIDE) * 4)

__device__ __forceinline__ float sigmoid_fast(float x) {
    return __fdividef(1.0f, 1.0f + __expf(-x));
}
__device__ __forceinline__ float tanh_fast(float x) {
    return 1.0f - __fdividef(2.0f, __expf(2.0f * x) + 1.0f);
}
__device__ __forceinline__ uint32_t smem_addr_u32(const void* p) {
    uint32_t a;
    asm("{ .reg .u64 t; cvta.to.shared.u64 t, %1; cvt.u32.u64 %0, t; }"
        : "=r"(a) : "l"(p));
    return a;
}

__global__ void __launch_bounds__(TPB, 1) lstm_rec_cluster(
    const float* __restrict__ Whh, float* __restrict__ out)
{
    extern __shared__ float smem[];
    float* hs  = smem;                      // [2][HBUF_WORDS] parity-tagged h
    float* wsm = smem + 2 * HBUF_WORDS;     // [TPB][WSM_STRIDE] gate2/3 weights

    const int tid  = threadIdx.x;
    const int w    = tid >> 5;
    const int l    = tid & 31;
    const int half = l >> 4;
    const int hl   = l & 15;
    uint32_t r;
    asm("mov.u32 %0, %%cluster_ctarank;" : "=r"(r));

    const int u  = (int)r * UPC + 2 * w + half;  // owned unit
    const int c0 = hl * 32;                      // columns for this lane

    // Load weights: gates 0,1 -> registers; gates 2,3 -> own smem
    float wr0[32], wr1[32];
    {
        const float* p0 = Whh + ((size_t)(0 * HDIM + u)) * HDIM + c0;
        const float* p1 = Whh + ((size_t)(1 * HDIM + u)) * HDIM + c0;
#pragma unroll
        for (int k = 0; k < 32; k += 4) {
            float4 v = *(const float4*)(p0 + k);
            wr0[k] = v.x; wr0[k+1] = v.y; wr0[k+2] = v.z; wr0[k+3] = v.w;
        }
#pragma unroll
        for (int k = 0; k < 32; k += 4) {
            float4 v = *(const float4*)(p1 + k);
            wr1[k] = v.x; wr1[k+1] = v.y; wr1[k+2] = v.z; wr1[k+3] = v.w;
        }
        const float* p2 = Whh + ((size_t)(2 * HDIM + u)) * HDIM + c0;
        const float* p3 = Whh + ((size_t)(3 * HDIM + u)) * HDIM + c0;
        float* wp = wsm + tid * WSM_STRIDE;
        for (int k = 0; k < 32; k++) wp[k]      = p2[k];
        for (int k = 0; k < 32; k++) wp[32 + k] = p3[k];
    }

    // Init h ring with LSB=1 (first two consumes expect parity 0 -> no false+)
    for (int i = tid; i < 2 * HBUF_WORDS; i += TPB)
        ((uint32_t*)hs)[i] = 1u;
    __syncthreads();
    // Cluster barrier: all CTAs' rings initialized before any remote push
    asm volatile("barrier.cluster.arrive.aligned;" ::: "memory");
    asm volatile("barrier.cluster.wait.aligned;"   ::: "memory");

    const uint32_t hs_base = smem_addr_u32(hs);
    // My push target: unit u's padded word in CTA rank==hl's ring
    const int push_word = u + ((u >> 5) << 2);
    uint32_t rem0, rem1;
    {
        uint32_t loc0 = hs_base + (uint32_t)(0 * HBUF_WORDS + push_word) * 4u;
        uint32_t loc1 = hs_base + (uint32_t)(1 * HBUF_WORDS + push_word) * 4u;
        asm("mapa.shared::cluster.u32 %0, %1, %2;"
            : "=r"(rem0) : "r"(loc0), "r"((uint32_t)hl));
        asm("mapa.shared::cluster.u32 %0, %1, %2;"
            : "=r"(rem1) : "r"(loc1), "r"((uint32_t)hl));
    }

    const float* wsp = wsm + tid * WSM_STRIDE;
    float c_state = 0.0f;     // redundantly maintained by all lanes (identical)

    // xg pipeline: lanes hl<4 hold gate hl's pre-activation, one step ahead
    const bool xlane = (hl < 4);
    const float* xbase = g_xgates + (size_t)hl * HDIM + u;
    float xg_cur = 0.0f;
    if (xlane)
        asm volatile("ld.global.cs.b32 %0, [%1];" : "=f"(xg_cur) : "l"(xbase));

    for (int t = 0; t < T_SEQ; t++) {
        float xg_nxt = 0.0f;
        if (xlane) {
            const float* xr = xbase + (size_t)((t + 1 < T_SEQ) ? t + 1 : t) * G4;
            asm volatile("ld.global.cs.b32 %0, [%1];" : "=f"(xg_nxt) : "l"(xr));
        }

        // ---- acquire h_{t-1} from OWN smem (pushed by all CTAs) ----
        float hv[32];
        if (t > 0) {
            const uint32_t pa  = hs_base +
                (uint32_t)(((t - 1) & 1) * HBUF_WORDS + 36 * hl) * 4u;
            const uint32_t par = ((uint32_t)(t - 1) >> 1) & 1u;
            while (true) {
#pragma unroll
                for (int k = 0; k < 8; k++) {
                    asm volatile("ld.volatile.shared.v4.f32 {%0,%1,%2,%3}, [%4];"
                        : "=f"(hv[k*4]), "=f"(hv[k*4+1]),
                          "=f"(hv[k*4+2]), "=f"(hv[k*4+3])
                        : "r"(pa + (uint32_t)k * 16u));
                }
                uint32_t bad = 0;
#pragma unroll
                for (int k = 0; k < 32; k++)
                    bad |= (__float_as_uint(hv[k]) ^ par);
                if ((bad & 1u) == 0u) break;
            }
        } else {
#pragma unroll
            for (int k = 0; k < 32; k++) hv[k] = 0.0f;
        }

        // ---- matvec: 4 gates x 32 cols directly from polled registers ----
        float a0 = 0.f, a1 = 0.f, a2 = 0.f, a3 = 0.f;
#pragma unroll
        for (int k = 0; k < 32; k += 4) {
            float4 w2 = *(const float4*)(wsp + k);
            float4 w3 = *(const float4*)(wsp + 32 + k);
            a0 = fmaf(wr0[k+0], hv[k+0], a0); a1 = fmaf(wr1[k+0], hv[k+0], a1);
            a2 = fmaf(w2.x,     hv[k+0], a2); a3 = fmaf(w3.x,     hv[k+0], a3);
            a0 = fmaf(wr0[k+1], hv[k+1], a0); a1 = fmaf(wr1[k+1], hv[k+1], a1);
            a2 = fmaf(w2.y,     hv[k+1], a2); a3 = fmaf(w3.y,     hv[k+1], a3);
            a0 = fmaf(wr0[k+2], hv[k+2], a0); a1 = fmaf(wr1[k+2], hv[k+2], a1);
            a2 = fmaf(w2.z,     hv[k+2], a2); a3 = fmaf(w3.z,     hv[k+2], a3);
            a0 = fmaf(wr0[k+3], hv[k+3], a0); a1 = fmaf(wr1[k+3], hv[k+3], a1);
            a2 = fmaf(w2.w,     hv[k+3], a2); a3 = fmaf(w3.w,     hv[k+3], a3);
        }
        // 4-level butterfly within the half-warp (xor<16 stays in half)
#pragma unroll
        for (int off = 8; off >= 1; off >>= 1) {
            a0 += __shfl_xor_sync(0xffffffffu, a0, off);
            a1 += __shfl_xor_sync(0xffffffffu, a1, off);
            a2 += __shfl_xor_sync(0xffffffffu, a2, off);
            a3 += __shfl_xor_sync(0xffffffffu, a3, off);
        }

        // ---- activations (lanes base+0..3 in parallel, MUFU path) ----
        float act = 0.0f;
        if (xlane) {
            float pre = (hl == 0 ? a0 : hl == 1 ? a1 : hl == 2 ? a2 : a3) + xg_cur;
            act = (hl == 2) ? tanh_fast(pre) : sigmoid_fast(pre);
        }
        const int base = half << 4;
        float iv = __shfl_sync(0xffffffffu, act, base + 0);
        float fv = __shfl_sync(0xffffffffu, act, base + 1);
        float gv = __shfl_sync(0xffffffffu, act, base + 2);
        float ov = __shfl_sync(0xffffffffu, act, base + 3);

        // All lanes update c identically (deterministic, stays consistent)
        c_state = fv * c_state + iv * gv;
        float hval = ov * tanh_fast(c_state);
        uint32_t hb = (__float_as_uint(hval) & ~1u) | (((uint32_t)t >> 1) & 1u);

        // ---- push: lane hl delivers unit u to CTA rank hl (16 lanes = 16 CTAs)
        uint32_t rem = (t & 1) ? rem1 : rem0;
        asm volatile("st.relaxed.cluster.shared::cluster.b32 [%0], %1;"
                     :: "r"(rem), "r"(hb) : "memory");
        if (hl == 0) {
            asm volatile("st.global.cs.b32 [%0], %1;"
                         :: "l"(out + (size_t)t * HDIM + u), "r"(hb) : "memory");
        }
        xg_cur = xg_nxt;
    }

    // EXIT RACE FIX (the R9 crash): no CTA may retire while peer CTAs can
    // still push into its SMEM ring.  Hold everyone until all final-step
    // stores have been issued by every CTA.
    asm volatile("barrier.cluster.arrive.aligned;" ::: "memory");
    asm volatile("barrier.cluster.wait.aligned;"   ::: "memory");
}

// ---------------------------------------------------------------------------
extern "C" void kernel_launch(void* const* d_in, const int* in_sizes, int n_in,
                              void* d_out, int out_size) {
    const float* input = (const float*)d_in[0];  // [T, H]
    const float* w_ih  = (const float*)d_in[1];  // [4H, H]
    const float* w_hh  = (const float*)d_in[2];  // [4H, H]
    const float* b_ih  = (const float*)d_in[3];  // [4H]
    float* out = (float*)d_out;                  // [T, H]
    (void)in_sizes; (void)n_in; (void)out_size;

    dim3 gg(G4 / 128, T_SEQ / 128);
    gemm_xgates_kernel<<<gg, 256>>>(input, w_ih, b_ih);

    // Cluster launch (idempotent attribute setters; executed at capture time)
    cudaFuncSetAttribute(lstm_rec_cluster,
                         cudaFuncAttributeNonPortableClusterSizeAllowed, 1);
    cudaFuncSetAttribute(lstm_rec_cluster,
                         cudaFuncAttributeMaxDynamicSharedMemorySize, SMEM_BYTES);

    cudaLaunchConfig_t cfg = {};
    cfg.gridDim  = dim3(NC, 1, 1);
    cfg.blockDim = dim3(TPB, 1, 1);
    cfg.dynamicSmemBytes = SMEM_BYTES;
    cfg.stream = 0;
    cudaLaunchAttribute attrs[1];
    attrs[0].id = cudaLaunchAttributeClusterDimension;
    attrs[0].val.clusterDim.x = NC;
    attrs[0].val.clusterDim.y = 1;
    attrs[0].val.clusterDim.z = 1;
    cfg.attrs = attrs;
    cfg.numAttrs = 1;
    cudaLaunchKernelEx(&cfg, lstm_rec_cluster, w_hh, out);
}